// round 13
// baseline (speedup 1.0000x reference)
#include <cuda_runtime.h>
#include <cuda_bf16.h>
#include <cstdint>

#define NN 100000
#define DD 128
#define CC 47
#define EMAX 1700000
#define NBLK 128

// unified zeroed scratch: deg[0:NN), sync ctr, sums[SUM_OFF: 3*256)
#define DEG_OFF  0
#define SYNC_OFF 100032
#define SUM_OFF  100160
#define ZR_INTS  (SUM_OFF + 3 * 256)

__device__ __align__(128) int   g_zr[ZR_INTS];
__device__ __align__(128) int   g_bsum[128];
__device__ __align__(128) float g_h[(size_t)NN * DD];
__device__ __align__(128) __nv_bfloat16 g_xhi[(size_t)NN * DD];
__device__ __align__(128) __nv_bfloat16 g_xlo[(size_t)NN * DD];
__device__ __align__(128) __nv_bfloat16 g_mhi[(size_t)NN * DD];
__device__ __align__(128) __nv_bfloat16 g_mlo[(size_t)NN * DD];
__device__ __align__(128) __nv_bfloat16 g_whi[3 * 2 * DD * DD];
__device__ __align__(128) __nv_bfloat16 g_wlo[3 * 2 * DD * DD];
__device__ __align__(128) int   g_rowptr[NN];
__device__ __align__(128) int   g_cursor[NN];
__device__ __align__(128) int   g_srcs[EMAX];

__device__ __forceinline__ void split_bf16(float v, __nv_bfloat16& hi, __nv_bfloat16& lo) {
    hi = __float2bfloat16(v);
    lo = __float2bfloat16(v - __bfloat162float(hi));
}
__device__ __forceinline__ uint32_t smem_to_u32(const void* p) {
    uint32_t a;
    asm("{ .reg .u64 t; cvta.to.shared.u64 t, %1; cvt.u32.u64 %0, t; }"
        : "=r"(a) : "l"(p));
    return a;
}
__device__ __forceinline__ void ldsm_x4(uint32_t* r, uint32_t addr) {
    asm volatile("ldmatrix.sync.aligned.m8n8.x4.shared.b16 {%0,%1,%2,%3}, [%4];"
                 : "=r"(r[0]), "=r"(r[1]), "=r"(r[2]), "=r"(r[3])
                 : "r"(addr));
}
__device__ __forceinline__ void mma_bf16(float* d, const uint32_t* a, const uint32_t* b) {
    asm volatile(
        "mma.sync.aligned.m16n8k16.row.col.f32.bf16.bf16.f32 "
        "{%0,%1,%2,%3}, {%4,%5,%6,%7}, {%8,%9}, {%0,%1,%2,%3};"
        : "+f"(d[0]), "+f"(d[1]), "+f"(d[2]), "+f"(d[3])
        : "r"(a[0]), "r"(a[1]), "r"(a[2]), "r"(a[3]), "r"(b[0]), "r"(b[1]));
}
__device__ __forceinline__ void cpa16(uint32_t dst, const void* src, int nbytes) {
    asm volatile("cp.async.cg.shared.global [%0], [%1], 16, %2;"
                 :: "r"(dst), "l"(src), "r"(nbytes));
}

extern __shared__ char dynsm[];

// ---------------- fused: zero scratch + x → hi/lo + all weights → hi/lo -----
__global__ void convert_kernel(const float4* __restrict__ x4,
                               const float* __restrict__ Wl1, const float* __restrict__ Wr1,
                               const float* __restrict__ Wl2, const float* __restrict__ Wr2,
                               const float* __restrict__ Wl3, const float* __restrict__ Wr3) {
    int i = blockIdx.x * blockDim.x + threadIdx.x;
    if (i < NN * 32) {
        float4 v = __ldg(x4 + i);
        __nv_bfloat16 h[4], l[4];
        split_bf16(v.x, h[0], l[0]); split_bf16(v.y, h[1], l[1]);
        split_bf16(v.z, h[2], l[2]); split_bf16(v.w, h[3], l[3]);
        size_t o2 = (size_t)i * 2;
        ((__nv_bfloat162*)g_xhi)[o2]     = __nv_bfloat162(h[0], h[1]);
        ((__nv_bfloat162*)g_xhi)[o2 + 1] = __nv_bfloat162(h[2], h[3]);
        ((__nv_bfloat162*)g_xlo)[o2]     = __nv_bfloat162(l[0], l[1]);
        ((__nv_bfloat162*)g_xlo)[o2 + 1] = __nv_bfloat162(l[2], l[3]);
        return;
    }
    int j = i - NN * 32;
    if (j < 3 * 2 * DD * DD) {
        int l    = j >> 15;
        int rem  = j & 32767;
        int half = rem >> 14;
        int id   = rem & 16383;
        int col  = id >> 7, k = id & 127;
        const float* tab[6] = {Wl1, Wr1, Wl2, Wr2, Wl3, Wr3};
        float v = __ldg(tab[l * 2 + half] + id);
        int pos = l * 32768 + col * 256 + half * 128 + k;
        __nv_bfloat16 h, lo;
        split_bf16(v, h, lo);
        g_whi[pos] = h;
        g_wlo[pos] = lo;
        return;
    }
    int z = j - 3 * 2 * DD * DD;
    if (z < ZR_INTS) g_zr[z] = 0;
}
#define CONV_TOTAL (NN * 32 + 3 * 2 * DD * DD + ZR_INTS)

// ---------------- persistent CSR build: deg → scan → rowptr → fill ----------
__device__ __forceinline__ void gbar(int target) {
    __syncthreads();
    __threadfence();
    if (threadIdx.x == 0) {
        atomicAdd(&g_zr[SYNC_OFF], 1);
        while (atomicAdd(&g_zr[SYNC_OFF], 0) < target) {}
    }
    __syncthreads();
}

__global__ __launch_bounds__(1024) void csr_kernel(const int* __restrict__ src,
                                                   const int* __restrict__ dst, int E) {
    __shared__ int sm[1024];
    __shared__ int sb2[128];
    __shared__ int sprev;
    int tid = threadIdx.x, b = blockIdx.x;
    int gid = b * 1024 + tid, gstride = NBLK * 1024;

    for (int e = gid; e < E; e += gstride)
        atomicAdd(&g_zr[DEG_OFF + __ldg(dst + e)], 1);
    gbar(NBLK);

    int v = 0;
    if (b < 98) {
        int i = b * 1024 + tid;
        v = (i < NN) ? g_zr[DEG_OFF + i] : 0;
        sm[tid] = v;
        __syncthreads();
        for (int off = 1; off < 1024; off <<= 1) {
            int u = (tid >= off) ? sm[tid - off] : 0;
            __syncthreads();
            sm[tid] += u;
            __syncthreads();
        }
        if (tid == 1023) g_bsum[b] = sm[1023];
    }
    gbar(2 * NBLK);

    if (b < 98) {
        if (tid < 128) sb2[tid] = (tid < 98) ? g_bsum[tid] : 0;
        __syncthreads();
        if (tid == 0) {
            int r = 0;
            for (int j = 0; j < b; j++) r += sb2[j];
            sprev = r;
        }
        __syncthreads();
        int i = b * 1024 + tid;
        if (i < NN) {
            int r = sprev + sm[tid] - v;
            g_rowptr[i] = r;
            g_cursor[i] = r;
        }
    }
    gbar(3 * NBLK);

    for (int e = gid; e < E; e += gstride) {
        int d = __ldg(dst + e);
        int pos = atomicAdd(&g_cursor[d], 1);
        g_srcs[pos] = __ldg(src + e);
    }
}

// ---------------- layer-1 gather: fp32 x → (mhi,mlo), MLP 8 -----------------
__global__ void gather_f32_kernel(const float4* __restrict__ x4) {
    int node = (blockIdx.x * blockDim.x + threadIdx.x) >> 5;
    int lane = threadIdx.x & 31;
    if (node >= NN) return;
    int i = g_rowptr[node], deg = g_zr[DEG_OFF + node], end = i + deg;
    float4 a0 = make_float4(0.f, 0.f, 0.f, 0.f);
    float4 a1 = a0, a2 = a0, a3 = a0;
    for (; i + 8 <= end; i += 8) {
        int s[8];
#pragma unroll
        for (int u = 0; u < 8; u++) s[u] = __ldg(&g_srcs[i + u]);
        float4 v[8];
#pragma unroll
        for (int u = 0; u < 8; u++) v[u] = __ldg(x4 + (size_t)s[u] * 32 + lane);
#pragma unroll
        for (int u = 0; u < 8; u += 4) {
            a0.x += v[u].x;   a0.y += v[u].y;   a0.z += v[u].z;   a0.w += v[u].w;
            a1.x += v[u+1].x; a1.y += v[u+1].y; a1.z += v[u+1].z; a1.w += v[u+1].w;
            a2.x += v[u+2].x; a2.y += v[u+2].y; a2.z += v[u+2].z; a2.w += v[u+2].w;
            a3.x += v[u+3].x; a3.y += v[u+3].y; a3.z += v[u+3].z; a3.w += v[u+3].w;
        }
    }
    for (; i < end; i++) {
        int s = __ldg(&g_srcs[i]);
        float4 v = __ldg(x4 + (size_t)s * 32 + lane);
        a0.x += v.x; a0.y += v.y; a0.z += v.z; a0.w += v.w;
    }
    float iv = 1.f / fmaxf((float)deg, 1.f);
    float m[4];
    m[0] = (a0.x + a1.x + a2.x + a3.x) * iv;
    m[1] = (a0.y + a1.y + a2.y + a3.y) * iv;
    m[2] = (a0.z + a1.z + a2.z + a3.z) * iv;
    m[3] = (a0.w + a1.w + a2.w + a3.w) * iv;
    __nv_bfloat16 h[4], l[4];
#pragma unroll
    for (int j = 0; j < 4; j++) split_bf16(m[j], h[j], l[j]);
    size_t o2 = (size_t)node * 64 + lane * 2;
    ((__nv_bfloat162*)g_mhi)[o2]     = __nv_bfloat162(h[0], h[1]);
    ((__nv_bfloat162*)g_mhi)[o2 + 1] = __nv_bfloat162(h[2], h[3]);
    ((__nv_bfloat162*)g_mlo)[o2]     = __nv_bfloat162(l[0], l[1]);
    ((__nv_bfloat162*)g_mlo)[o2 + 1] = __nv_bfloat162(l[2], l[3]);
}

// ---------------- layers 2-3 gather: (xhi,xlo) → (mhi,mlo), MLP 8 -----------
__global__ void gather_bf_kernel() {
    int node = (blockIdx.x * blockDim.x + threadIdx.x) >> 5;
    int lane = threadIdx.x & 31;
    if (node >= NN) return;
    int seg = lane & 15;
    const uint4* base = (lane < 16) ? (const uint4*)g_xhi : (const uint4*)g_xlo;
    int i = g_rowptr[node], deg = g_zr[DEG_OFF + node], end = i + deg;
    float acc[8];
#pragma unroll
    for (int f = 0; f < 8; f++) acc[f] = 0.f;

    for (; i + 8 <= end; i += 8) {
        int s[8];
#pragma unroll
        for (int u = 0; u < 8; u++) s[u] = __ldg(&g_srcs[i + u]);
        uint4 v[8];
#pragma unroll
        for (int u = 0; u < 8; u++) v[u] = __ldg(base + (size_t)s[u] * 16 + seg);
#pragma unroll
        for (int u = 0; u < 8; u++) {
            const __nv_bfloat162* p = (const __nv_bfloat162*)&v[u];
#pragma unroll
            for (int q = 0; q < 4; q++) {
                float2 f = __bfloat1622float2(p[q]);
                acc[2 * q] += f.x; acc[2 * q + 1] += f.y;
            }
        }
    }
    for (; i < end; i++) {
        int s = __ldg(&g_srcs[i]);
        uint4 v = __ldg(base + (size_t)s * 16 + seg);
        const __nv_bfloat162* p = (const __nv_bfloat162*)&v;
#pragma unroll
        for (int q = 0; q < 4; q++) {
            float2 f = __bfloat1622float2(p[q]);
            acc[2 * q] += f.x; acc[2 * q + 1] += f.y;
        }
    }

    float iv = 1.f / fmaxf((float)deg, 1.f);
    uint32_t outw[4];
#pragma unroll
    for (int q = 0; q < 4; q++) {
        float m0 = (acc[2 * q]     + __shfl_xor_sync(0xffffffffu, acc[2 * q],     16)) * iv;
        float m1 = (acc[2 * q + 1] + __shfl_xor_sync(0xffffffffu, acc[2 * q + 1], 16)) * iv;
        __nv_bfloat16 h0, l0, h1, l1;
        split_bf16(m0, h0, l0);
        split_bf16(m1, h1, l1);
        __nv_bfloat162 pk = (lane < 16) ? __nv_bfloat162(h0, h1) : __nv_bfloat162(l0, l1);
        outw[q] = *(uint32_t*)&pk;
    }
    uint4* dstA = (lane < 16) ? (uint4*)g_mhi : (uint4*)g_mlo;
    dstA[(size_t)node * 16 + seg] = make_uint4(outw[0], outw[1], outw[2], outw[3]);
}

// ---------------- pipelined HMMA split-bf16 GEMM ----------------------------
#define ROWB 80
#define TILE_B (128 * ROWB)
#define ST_A_HI 0
#define ST_A_LO TILE_B
#define ST_B_HI (2 * TILE_B)
#define ST_B_LO (3 * TILE_B)
#define STAGE_B (4 * TILE_B)

__device__ __forceinline__ void load_chunk(uint32_t sb, int stage, int kc,
                                           int row0, int tid,
                                           const uint4* whi4, const uint4* wlo4) {
    uint32_t sbase = sb + stage * STAGE_B;
    const uint4* aH = (kc < 4) ? (const uint4*)g_xhi : (const uint4*)g_mhi;
    const uint4* aL = (kc < 4) ? (const uint4*)g_xlo : (const uint4*)g_mlo;
    int ku = (kc & 3) * 4;
#pragma unroll
    for (int l = 0; l < 2; l++) {
        int idx = tid + l * 256;
        int r = idx >> 2, c = idx & 3;
        int grow = row0 + r;
        int nb = (grow < NN) ? 16 : 0;
        size_t srow = (size_t)min(grow, NN - 1) * 16;
        uint32_t d = sbase + r * ROWB + c * 16;
        cpa16(d + ST_A_HI, aH + srow + ku + c, nb);
        cpa16(d + ST_A_LO, aL + srow + ku + c, nb);
        cpa16(d + ST_B_HI, whi4 + r * 32 + kc * 4 + c, 16);
        cpa16(d + ST_B_LO, wlo4 + r * 32 + kc * 4 + c, 16);
    }
    asm volatile("cp.async.commit_group;" ::: "memory");
}

__global__ __launch_bounds__(256, 2) void gemm_mma_kernel(int layer) {
    char* sm = dynsm;
    uint32_t sb = smem_to_u32(sm);
    __shared__ float ssum[DD], ssum2[DD];

    int tid = threadIdx.x, lane = tid & 31, wid = tid >> 5;
    int row0 = blockIdx.x * 128;
    int wr = wid >> 1, wc = wid & 1;
    if (tid < DD) { ssum[tid] = 0.f; ssum2[tid] = 0.f; }

    const uint4* whi4 = (const uint4*)g_whi + layer * 4096;
    const uint4* wlo4 = (const uint4*)g_wlo + layer * 4096;

    float acc[2][8][4];
#pragma unroll
    for (int bm = 0; bm < 2; bm++)
#pragma unroll
        for (int j = 0; j < 8; j++)
#pragma unroll
            for (int q = 0; q < 4; q++) acc[bm][j][q] = 0.f;

    int a_min  = lane & 15;
    int a_koff = (lane >> 4) * 16;
    int b_nin  = (lane & 7) + ((lane >> 4) & 1) * 8;
    int b_koff = ((lane >> 3) & 1) * 16;

    load_chunk(sb, 0, 0, row0, tid, whi4, wlo4);

    for (int kc = 0; kc < 8; kc++) {
        int st = kc & 1;
        if (kc < 7) {
            load_chunk(sb, st ^ 1, kc + 1, row0, tid, whi4, wlo4);
            asm volatile("cp.async.wait_group 1;" ::: "memory");
        } else {
            asm volatile("cp.async.wait_group 0;" ::: "memory");
        }
        __syncthreads();

        uint32_t sbase = sb + st * STAGE_B;
#pragma unroll
        for (int ks = 0; ks < 2; ks++) {
            uint32_t aoff = (uint32_t)((wr * 32 + a_min) * ROWB + ks * 32 + a_koff);
            uint32_t boff0 = (uint32_t)((wc * 64 + b_nin) * ROWB + ks * 32 + b_koff);

            uint32_t ah[2][4], al[2][4], bh[8][2], bl[8][2];
#pragma unroll
            for (int bm = 0; bm < 2; bm++)
                ldsm_x4(ah[bm], sbase + ST_A_HI + aoff + bm * 16 * ROWB);
#pragma unroll
            for (int jp = 0; jp < 4; jp++) {
                uint32_t t[4];
                ldsm_x4(t, sbase + ST_B_HI + boff0 + jp * 16 * ROWB);
                bh[jp * 2][0] = t[0]; bh[jp * 2][1] = t[1];
                bh[jp * 2 + 1][0] = t[2]; bh[jp * 2 + 1][1] = t[3];
            }
#pragma unroll
            for (int bm = 0; bm < 2; bm++)
#pragma unroll
                for (int j = 0; j < 8; j++) mma_bf16(acc[bm][j], ah[bm], bh[j]);
#pragma unroll
            for (int jp = 0; jp < 4; jp++) {
                uint32_t t[4];
                ldsm_x4(t, sbase + ST_B_LO + boff0 + jp * 16 * ROWB);
                bl[jp * 2][0] = t[0]; bl[jp * 2][1] = t[1];
                bl[jp * 2 + 1][0] = t[2]; bl[jp * 2 + 1][1] = t[3];
            }
#pragma unroll
            for (int bm = 0; bm < 2; bm++)
#pragma unroll
                for (int j = 0; j < 8; j++) mma_bf16(acc[bm][j], ah[bm], bl[j]);
#pragma unroll
            for (int bm = 0; bm < 2; bm++)
                ldsm_x4(al[bm], sbase + ST_A_LO + aoff + bm * 16 * ROWB);
#pragma unroll
            for (int bm = 0; bm < 2; bm++)
#pragma unroll
                for (int j = 0; j < 8; j++) mma_bf16(acc[bm][j], al[bm], bh[j]);
        }
        __syncthreads();
    }

    int mrow = wr * 32, ncol = wc * 64;
    float cs[16], cs2[16];
#pragma unroll
    for (int t = 0; t < 16; t++) { cs[t] = 0.f; cs2[t] = 0.f; }

#pragma unroll
    for (int bm = 0; bm < 2; bm++) {
        int r_lo = row0 + mrow + bm * 16 + (lane >> 2);
        int r_hi = r_lo + 8;
#pragma unroll
        for (int j = 0; j < 8; j++) {
            int cb = ncol + j * 8 + (lane & 3) * 2;
            float v0 = acc[bm][j][0], v1 = acc[bm][j][1];
            float v2 = acc[bm][j][2], v3 = acc[bm][j][3];
            cs[j * 2]      += v0 + v2;
            cs2[j * 2]     += v0 * v0 + v2 * v2;
            cs[j * 2 + 1]  += v1 + v3;
            cs2[j * 2 + 1] += v1 * v1 + v3 * v3;
            if (r_lo < NN)
                *(float2*)(g_h + (size_t)r_lo * DD + cb) = make_float2(v0, v1);
            if (r_hi < NN)
                *(float2*)(g_h + (size_t)r_hi * DD + cb) = make_float2(v2, v3);
        }
    }
#pragma unroll
    for (int t = 0; t < 16; t++) {
        cs[t]  += __shfl_xor_sync(0xffffffffu, cs[t], 4);
        cs[t]  += __shfl_xor_sync(0xffffffffu, cs[t], 8);
        cs[t]  += __shfl_xor_sync(0xffffffffu, cs[t], 16);
        cs2[t] += __shfl_xor_sync(0xffffffffu, cs2[t], 4);
        cs2[t] += __shfl_xor_sync(0xffffffffu, cs2[t], 8);
        cs2[t] += __shfl_xor_sync(0xffffffffu, cs2[t], 16);
    }
    if (lane < 4) {
#pragma unroll
        for (int j = 0; j < 8; j++) {
#pragma unroll
            for (int t = 0; t < 2; t++) {
                int col = ncol + j * 8 + lane * 2 + t;
                atomicAdd(&ssum[col],  cs[j * 2 + t]);
                atomicAdd(&ssum2[col], cs2[j * 2 + t]);
            }
        }
    }
    __syncthreads();
    float* sums = (float*)g_zr + SUM_OFF + layer * 256;
    if (tid < DD) {
        atomicAdd(&sums[tid],       ssum[tid]);
        atomicAdd(&sums[tid + DD],  ssum2[tid]);
    }
}

// ---------------- BN (stats from per-layer slots) + ReLU + residual ---------
__global__ void bnfin_kernel(int layer,
                             const float* __restrict__ gamma,
                             const float* __restrict__ beta) {
    __shared__ float s_scale[DD], s_shift[DD];
    int tid = threadIdx.x;
    if (tid < DD) {
        const float* sums = (const float*)g_zr + SUM_OFF + layer * 256;
        float invN = 1.0f / (float)NN;
        float mu  = sums[tid] * invN;
        float var = sums[tid + DD] * invN - mu * mu;
        float a   = __ldg(gamma + tid) * rsqrtf(var + 1e-5f);
        s_scale[tid] = a;
        s_shift[tid] = __ldg(beta + tid) - mu * a;
    }
    __syncthreads();

    int i = blockIdx.x * blockDim.x + tid;
    if (i >= NN * 16) return;
    int seg = i & 15;
    uint4 vh = ((const uint4*)g_xhi)[i];
    uint4 vl = ((const uint4*)g_xlo)[i];
    const __nv_bfloat162* ph = (const __nv_bfloat162*)&vh;
    const __nv_bfloat162* pl = (const __nv_bfloat162*)&vl;
    int row = i >> 4;
    const float4* h4 = (const float4*)(g_h + (size_t)row * DD + seg * 8);
    float4 hv0 = h4[0], hv1 = h4[1];

    float xv[8], hh[8];
#pragma unroll
    for (int q = 0; q < 4; q++) {
        float2 fh = __bfloat1622float2(ph[q]);
        float2 fl = __bfloat1622float2(pl[q]);
        xv[2 * q] = fh.x + fl.x; xv[2 * q + 1] = fh.y + fl.y;
    }
    hh[0]=hv0.x; hh[1]=hv0.y; hh[2]=hv0.z; hh[3]=hv0.w;
    hh[4]=hv1.x; hh[5]=hv1.y; hh[6]=hv1.z; hh[7]=hv1.w;

    uint32_t oh[4], ol[4];
#pragma unroll
    for (int q = 0; q < 4; q++) {
        int c0 = seg * 8 + 2 * q, c1 = c0 + 1;
        float o0 = xv[2 * q]     + fmaxf(0.f, hh[2 * q]     * s_scale[c0] + s_shift[c0]);
        float o1 = xv[2 * q + 1] + fmaxf(0.f, hh[2 * q + 1] * s_scale[c1] + s_shift[c1]);
        __nv_bfloat16 h0, l0, h1, l1;
        split_bf16(o0, h0, l0);
        split_bf16(o1, h1, l1);
        __nv_bfloat162 pkh(h0, h1), pkl(l0, l1);
        oh[q] = *(uint32_t*)&pkh;
        ol[q] = *(uint32_t*)&pkl;
    }
    ((uint4*)g_xhi)[i] = make_uint4(oh[0], oh[1], oh[2], oh[3]);
    ((uint4*)g_xlo)[i] = make_uint4(ol[0], ol[1], ol[2], ol[3]);
}

// ---------------- final linear: row/thread, 47 register accumulators --------
__global__ __launch_bounds__(256) void final_kernel(
    const float* __restrict__ W,
    const float* __restrict__ bias,
    float* __restrict__ out) {
    __shared__ float Ws[CC * DD];
    __shared__ float bs[CC];
    int tid = threadIdx.x;
    int row = blockIdx.x * 256 + tid;

    for (int i = tid; i < CC * DD; i += 256) Ws[i] = __ldg(W + i);
    if (tid < CC) bs[tid] = __ldg(bias + tid);
    __syncthreads();

    if (row >= NN) return;

    float acc[CC];
#pragma unroll
    for (int c = 0; c < CC; c++) acc[c] = 0.f;

    for (int kc = 0; kc < 16; kc++) {
        uint4 vh = ((const uint4*)g_xhi)[(size_t)row * 16 + kc];
        uint4 vl = ((const uint4*)g_xlo)[(size_t)row * 16 + kc];
        const __nv_bfloat162* ph = (const __nv_bfloat162*)&vh;
        const __nv_bfloat162* pl = (const __nv_bfloat162*)&vl;
        float f[8];
#pragma unroll
        for (int q = 0; q < 4; q++) {
            float2 a = __bfloat1622float2(ph[q]);
            float2 b = __bfloat1622float2(pl[q]);
            f[2 * q] = a.x + b.x; f[2 * q + 1] = a.y + b.y;
        }
#pragma unroll
        for (int c = 0; c < CC; c++) {
            const float4* wr = (const float4*)&Ws[c * DD + kc * 8];
            float4 w0 = wr[0], w1 = wr[1];
            acc[c] += f[0] * w0.x + f[1] * w0.y + f[2] * w0.z + f[3] * w0.w
                    + f[4] * w1.x + f[5] * w1.y + f[6] * w1.z + f[7] * w1.w;
        }
    }
#pragma unroll
    for (int c = 0; c < CC; c++)
        out[(size_t)row * CC + c] = acc[c] + bs[c];
}

// ---------------- host orchestration ----------------------------------------
extern "C" void kernel_launch(void* const* d_in, const int* in_sizes, int n_in,
                              void* d_out, int out_size) {
    const float* x  = (const float*)d_in[0];
    const int*   ei = (const int*)d_in[1];
    int E = in_sizes[1] / 2;
    const int* src = ei;
    const int* dst = ei + E;

    const int SMEM_MMA = 2 * STAGE_B;
    cudaFuncSetAttribute(gemm_mma_kernel, cudaFuncAttributeMaxDynamicSharedMemorySize, SMEM_MMA);

    // 1: fused zero + x conversion + weight conversion
    convert_kernel<<<(CONV_TOTAL + 255) / 256, 256>>>(
        (const float4*)x,
        (const float*)d_in[2],  (const float*)d_in[4],
        (const float*)d_in[7],  (const float*)d_in[9],
        (const float*)d_in[12], (const float*)d_in[14]);
    // 2: CSR build
    csr_kernel<<<NBLK, 1024>>>(src, dst, E);
    // 3: layer-1 gather
    gather_f32_kernel<<<(NN * 32 + 255) / 256, 256>>>((const float4*)x);

    for (int L = 0; L < 3; L++) {
        const float* bg = (const float*)d_in[5 + 5 * L];
        const float* bb = (const float*)d_in[6 + 5 * L];
        if (L > 0) gather_bf_kernel<<<(NN * 32 + 255) / 256, 256>>>();
        // layer-0 GEMM is kernel launch #4 → ncu capture slot
        gemm_mma_kernel<<<(NN + 127) / 128, 256, SMEM_MMA>>>(L);
        bnfin_kernel<<<(NN * 16 + 255) / 256, 256>>>(L, bg, bb);
    }

    final_kernel<<<(NN + 255) / 256, 256>>>(
        (const float*)d_in[17], (const float*)d_in[18], (float*)d_out);
}

// round 15
// speedup vs baseline: 1.4433x; 1.4433x over previous
#include <cuda_runtime.h>
#include <cuda_bf16.h>
#include <cstdint>

#define NN 100000
#define DD 128
#define CC 47
#define EMAX 1700000
#define NBLK 128

// unified zeroed scratch: deg[0:NN), sync ctr, sums[SUM_OFF: 3*256)
#define DEG_OFF  0
#define SYNC_OFF 100032
#define SUM_OFF  100160
#define ZR_INTS  (SUM_OFF + 3 * 256)

__device__ __align__(128) int   g_zr[ZR_INTS];
__device__ __align__(128) int   g_bsum[128];
__device__ __align__(128) float g_h[(size_t)NN * DD];
__device__ __align__(128) __nv_bfloat16 g_xhi[(size_t)NN * DD];
__device__ __align__(128) __nv_bfloat16 g_xlo[(size_t)NN * DD];
__device__ __align__(128) __nv_bfloat16 g_mhi[(size_t)NN * DD];
__device__ __align__(128) __nv_bfloat16 g_mlo[(size_t)NN * DD];
__device__ __align__(128) __nv_bfloat16 g_whi[3 * 2 * DD * DD];
__device__ __align__(128) __nv_bfloat16 g_wlo[3 * 2 * DD * DD];
__device__ __align__(128) int   g_rowptr[NN];
__device__ __align__(128) int   g_cursor[NN];
__device__ __align__(128) int   g_srcs[EMAX];

__device__ __forceinline__ void split_bf16(float v, __nv_bfloat16& hi, __nv_bfloat16& lo) {
    hi = __float2bfloat16(v);
    lo = __float2bfloat16(v - __bfloat162float(hi));
}
__device__ __forceinline__ uint32_t smem_to_u32(const void* p) {
    uint32_t a;
    asm("{ .reg .u64 t; cvta.to.shared.u64 t, %1; cvt.u32.u64 %0, t; }"
        : "=r"(a) : "l"(p));
    return a;
}
__device__ __forceinline__ void ldsm_x4(uint32_t* r, uint32_t addr) {
    asm volatile("ldmatrix.sync.aligned.m8n8.x4.shared.b16 {%0,%1,%2,%3}, [%4];"
                 : "=r"(r[0]), "=r"(r[1]), "=r"(r[2]), "=r"(r[3])
                 : "r"(addr));
}
__device__ __forceinline__ void mma_bf16(float* d, const uint32_t* a, const uint32_t* b) {
    asm volatile(
        "mma.sync.aligned.m16n8k16.row.col.f32.bf16.bf16.f32 "
        "{%0,%1,%2,%3}, {%4,%5,%6,%7}, {%8,%9}, {%0,%1,%2,%3};"
        : "+f"(d[0]), "+f"(d[1]), "+f"(d[2]), "+f"(d[3])
        : "r"(a[0]), "r"(a[1]), "r"(a[2]), "r"(a[3]), "r"(b[0]), "r"(b[1]));
}
__device__ __forceinline__ void cpa16(uint32_t dst, const void* src, int nbytes) {
    asm volatile("cp.async.cg.shared.global [%0], [%1], 16, %2;"
                 :: "r"(dst), "l"(src), "r"(nbytes));
}

extern __shared__ char dynsm[];

// ---------------- zero scratch ----------------------------------------------
__global__ void zero_kernel() {
    int i = blockIdx.x * blockDim.x + threadIdx.x;
    if (i < ZR_INTS) g_zr[i] = 0;
}

// ---------------- input x → hi/lo bf16 --------------------------------------
__global__ void xconv_kernel(const float4* __restrict__ x4) {
    int i = blockIdx.x * blockDim.x + threadIdx.x;
    if (i >= NN * 32) return;
    float4 v = __ldg(x4 + i);
    __nv_bfloat16 h[4], l[4];
    split_bf16(v.x, h[0], l[0]); split_bf16(v.y, h[1], l[1]);
    split_bf16(v.z, h[2], l[2]); split_bf16(v.w, h[3], l[3]);
    size_t o2 = (size_t)i * 2;
    ((__nv_bfloat162*)g_xhi)[o2]     = __nv_bfloat162(h[0], h[1]);
    ((__nv_bfloat162*)g_xhi)[o2 + 1] = __nv_bfloat162(h[2], h[3]);
    ((__nv_bfloat162*)g_xlo)[o2]     = __nv_bfloat162(l[0], l[1]);
    ((__nv_bfloat162*)g_xlo)[o2 + 1] = __nv_bfloat162(l[2], l[3]);
}

// ---------------- all-layer weights → concat K-major hi/lo ------------------
__global__ void wconv_kernel(const float* __restrict__ Wl1, const float* __restrict__ Wr1,
                             const float* __restrict__ Wl2, const float* __restrict__ Wr2,
                             const float* __restrict__ Wl3, const float* __restrict__ Wr3) {
    int idx = blockIdx.x * blockDim.x + threadIdx.x;
    if (idx >= 3 * 2 * DD * DD) return;
    int l    = idx >> 15;
    int rem  = idx & 32767;
    int half = rem >> 14;
    int id   = rem & 16383;
    int col  = id >> 7, k = id & 127;
    const float* tab[6] = {Wl1, Wr1, Wl2, Wr2, Wl3, Wr3};
    float v = __ldg(tab[l * 2 + half] + id);
    int pos = l * 32768 + col * 256 + half * 128 + k;
    __nv_bfloat16 h, lo;
    split_bf16(v, h, lo);
    g_whi[pos] = h;
    g_wlo[pos] = lo;
}

// ---------------- persistent CSR build: deg → scan → rowptr → fill ----------
__device__ __forceinline__ void gbar(int target) {
    __syncthreads();
    __threadfence();
    if (threadIdx.x == 0) {
        atomicAdd(&g_zr[SYNC_OFF], 1);
        while (atomicAdd(&g_zr[SYNC_OFF], 0) < target) {}
    }
    __syncthreads();
}

__global__ __launch_bounds__(1024) void csr_kernel(const int* __restrict__ src,
                                                   const int* __restrict__ dst, int E) {
    __shared__ int sm[1024];
    __shared__ int sb2[128];
    __shared__ int sprev;
    int tid = threadIdx.x, b = blockIdx.x;
    int gid = b * 1024 + tid, gstride = NBLK * 1024;

    for (int e = gid; e < E; e += gstride)
        atomicAdd(&g_zr[DEG_OFF + __ldg(dst + e)], 1);
    gbar(NBLK);

    int v = 0;
    if (b < 98) {
        int i = b * 1024 + tid;
        v = (i < NN) ? g_zr[DEG_OFF + i] : 0;
        sm[tid] = v;
        __syncthreads();
        for (int off = 1; off < 1024; off <<= 1) {
            int u = (tid >= off) ? sm[tid - off] : 0;
            __syncthreads();
            sm[tid] += u;
            __syncthreads();
        }
        if (tid == 1023) g_bsum[b] = sm[1023];
    }
    gbar(2 * NBLK);

    if (b < 98) {
        if (tid < 128) sb2[tid] = (tid < 98) ? g_bsum[tid] : 0;
        __syncthreads();
        if (tid == 0) {
            int r = 0;
            for (int j = 0; j < b; j++) r += sb2[j];
            sprev = r;
        }
        __syncthreads();
        int i = b * 1024 + tid;
        if (i < NN) {
            int r = sprev + sm[tid] - v;
            g_rowptr[i] = r;
            g_cursor[i] = r;
        }
    }
    gbar(3 * NBLK);

    for (int e = gid; e < E; e += gstride) {
        int d = __ldg(dst + e);
        int pos = atomicAdd(&g_cursor[d], 1);
        g_srcs[pos] = __ldg(src + e);
    }
}

// ---------------- layer-1 gather: fp32 x → (mhi,mlo), MLP 4 -----------------
__global__ void gather_f32_kernel(const float4* __restrict__ x4) {
    int node = (blockIdx.x * blockDim.x + threadIdx.x) >> 5;
    int lane = threadIdx.x & 31;
    if (node >= NN) return;
    int i = g_rowptr[node], deg = g_zr[DEG_OFF + node], end = i + deg;
    float4 a0 = make_float4(0.f, 0.f, 0.f, 0.f);
    float4 a1 = a0, a2 = a0, a3 = a0;
    for (; i + 4 <= end; i += 4) {
        int s0 = __ldg(&g_srcs[i]);
        int s1 = __ldg(&g_srcs[i + 1]);
        int s2 = __ldg(&g_srcs[i + 2]);
        int s3 = __ldg(&g_srcs[i + 3]);
        float4 v0 = __ldg(x4 + (size_t)s0 * 32 + lane);
        float4 v1 = __ldg(x4 + (size_t)s1 * 32 + lane);
        float4 v2 = __ldg(x4 + (size_t)s2 * 32 + lane);
        float4 v3 = __ldg(x4 + (size_t)s3 * 32 + lane);
        a0.x += v0.x; a0.y += v0.y; a0.z += v0.z; a0.w += v0.w;
        a1.x += v1.x; a1.y += v1.y; a1.z += v1.z; a1.w += v1.w;
        a2.x += v2.x; a2.y += v2.y; a2.z += v2.z; a2.w += v2.w;
        a3.x += v3.x; a3.y += v3.y; a3.z += v3.z; a3.w += v3.w;
    }
    for (; i < end; i++) {
        int s = __ldg(&g_srcs[i]);
        float4 v = __ldg(x4 + (size_t)s * 32 + lane);
        a0.x += v.x; a0.y += v.y; a0.z += v.z; a0.w += v.w;
    }
    float iv = 1.f / fmaxf((float)deg, 1.f);
    float m[4];
    m[0] = (a0.x + a1.x + a2.x + a3.x) * iv;
    m[1] = (a0.y + a1.y + a2.y + a3.y) * iv;
    m[2] = (a0.z + a1.z + a2.z + a3.z) * iv;
    m[3] = (a0.w + a1.w + a2.w + a3.w) * iv;
    __nv_bfloat16 h[4], l[4];
#pragma unroll
    for (int j = 0; j < 4; j++) split_bf16(m[j], h[j], l[j]);
    size_t o2 = (size_t)node * 64 + lane * 2;
    ((__nv_bfloat162*)g_mhi)[o2]     = __nv_bfloat162(h[0], h[1]);
    ((__nv_bfloat162*)g_mhi)[o2 + 1] = __nv_bfloat162(h[2], h[3]);
    ((__nv_bfloat162*)g_mlo)[o2]     = __nv_bfloat162(l[0], l[1]);
    ((__nv_bfloat162*)g_mlo)[o2 + 1] = __nv_bfloat162(l[2], l[3]);
}

// ---------------- layers 2-3 gather: (xhi,xlo) → (mhi,mlo), MLP 4 -----------
__global__ void gather_bf_kernel() {
    int node = (blockIdx.x * blockDim.x + threadIdx.x) >> 5;
    int lane = threadIdx.x & 31;
    if (node >= NN) return;
    int seg = lane & 15;
    const uint4* base = (lane < 16) ? (const uint4*)g_xhi : (const uint4*)g_xlo;
    int i = g_rowptr[node], deg = g_zr[DEG_OFF + node], end = i + deg;
    float acc[8];
#pragma unroll
    for (int f = 0; f < 8; f++) acc[f] = 0.f;

    for (; i + 4 <= end; i += 4) {
        int s0 = __ldg(&g_srcs[i]);
        int s1 = __ldg(&g_srcs[i + 1]);
        int s2 = __ldg(&g_srcs[i + 2]);
        int s3 = __ldg(&g_srcs[i + 3]);
        uint4 v0 = __ldg(base + (size_t)s0 * 16 + seg);
        uint4 v1 = __ldg(base + (size_t)s1 * 16 + seg);
        uint4 v2 = __ldg(base + (size_t)s2 * 16 + seg);
        uint4 v3 = __ldg(base + (size_t)s3 * 16 + seg);
        const uint4* vs[4] = {&v0, &v1, &v2, &v3};
#pragma unroll
        for (int e2 = 0; e2 < 4; e2++) {
            const __nv_bfloat162* p = (const __nv_bfloat162*)vs[e2];
#pragma unroll
            for (int q = 0; q < 4; q++) {
                float2 f = __bfloat1622float2(p[q]);
                acc[2 * q] += f.x; acc[2 * q + 1] += f.y;
            }
        }
    }
    for (; i < end; i++) {
        int s = __ldg(&g_srcs[i]);
        uint4 v = __ldg(base + (size_t)s * 16 + seg);
        const __nv_bfloat162* p = (const __nv_bfloat162*)&v;
#pragma unroll
        for (int q = 0; q < 4; q++) {
            float2 f = __bfloat1622float2(p[q]);
            acc[2 * q] += f.x; acc[2 * q + 1] += f.y;
        }
    }

    float iv = 1.f / fmaxf((float)deg, 1.f);
    uint32_t outw[4];
#pragma unroll
    for (int q = 0; q < 4; q++) {
        float m0 = (acc[2 * q]     + __shfl_xor_sync(0xffffffffu, acc[2 * q],     16)) * iv;
        float m1 = (acc[2 * q + 1] + __shfl_xor_sync(0xffffffffu, acc[2 * q + 1], 16)) * iv;
        __nv_bfloat16 h0, l0, h1, l1;
        split_bf16(m0, h0, l0);
        split_bf16(m1, h1, l1);
        __nv_bfloat162 pk = (lane < 16) ? __nv_bfloat162(h0, h1) : __nv_bfloat162(l0, l1);
        outw[q] = *(uint32_t*)&pk;
    }
    uint4* dstA = (lane < 16) ? (uint4*)g_mhi : (uint4*)g_mlo;
    dstA[(size_t)node * 16 + seg] = make_uint4(outw[0], outw[1], outw[2], outw[3]);
}

// ---------------- pipelined HMMA split-bf16 GEMM (interleaved mainloop) -----
#define ROWB 80
#define TILE_B (128 * ROWB)
#define ST_A_HI 0
#define ST_A_LO TILE_B
#define ST_B_HI (2 * TILE_B)
#define ST_B_LO (3 * TILE_B)
#define STAGE_B (4 * TILE_B)

__device__ __forceinline__ void load_chunk(uint32_t sb, int stage, int kc,
                                           int row0, int tid,
                                           const uint4* whi4, const uint4* wlo4) {
    uint32_t sbase = sb + stage * STAGE_B;
    const uint4* aH = (kc < 4) ? (const uint4*)g_xhi : (const uint4*)g_mhi;
    const uint4* aL = (kc < 4) ? (const uint4*)g_xlo : (const uint4*)g_mlo;
    int ku = (kc & 3) * 4;
#pragma unroll
    for (int l = 0; l < 2; l++) {
        int idx = tid + l * 256;
        int r = idx >> 2, c = idx & 3;
        int grow = row0 + r;
        int nb = (grow < NN) ? 16 : 0;
        size_t srow = (size_t)min(grow, NN - 1) * 16;
        uint32_t d = sbase + r * ROWB + c * 16;
        cpa16(d + ST_A_HI, aH + srow + ku + c, nb);
        cpa16(d + ST_A_LO, aL + srow + ku + c, nb);
        cpa16(d + ST_B_HI, whi4 + r * 32 + kc * 4 + c, 16);
        cpa16(d + ST_B_LO, wlo4 + r * 32 + kc * 4 + c, 16);
    }
    asm volatile("cp.async.commit_group;" ::: "memory");
}

__global__ __launch_bounds__(256, 2) void gemm_mma_kernel(int layer) {
    char* sm = dynsm;
    uint32_t sb = smem_to_u32(sm);
    __shared__ float ssum[DD], ssum2[DD];

    int tid = threadIdx.x, lane = tid & 31, wid = tid >> 5;
    int row0 = blockIdx.x * 128;
    int wr = wid >> 1, wc = wid & 1;
    if (tid < DD) { ssum[tid] = 0.f; ssum2[tid] = 0.f; }

    const uint4* whi4 = (const uint4*)g_whi + layer * 4096;
    const uint4* wlo4 = (const uint4*)g_wlo + layer * 4096;

    float acc[2][8][4];
#pragma unroll
    for (int bm = 0; bm < 2; bm++)
#pragma unroll
        for (int j = 0; j < 8; j++)
#pragma unroll
            for (int q = 0; q < 4; q++) acc[bm][j][q] = 0.f;

    int a_min  = lane & 15;
    int a_koff = (lane >> 4) * 16;
    int b_nin  = (lane & 7) + ((lane >> 4) & 1) * 8;
    int b_koff = ((lane >> 3) & 1) * 16;

    load_chunk(sb, 0, 0, row0, tid, whi4, wlo4);

    const int pa[3] = {0, 0, 1};
    const int pb[3] = {0, 1, 0};

    for (int kc = 0; kc < 8; kc++) {
        int st = kc & 1;
        if (kc < 7) {
            load_chunk(sb, st ^ 1, kc + 1, row0, tid, whi4, wlo4);
            asm volatile("cp.async.wait_group 1;" ::: "memory");
        } else {
            asm volatile("cp.async.wait_group 0;" ::: "memory");
        }
        __syncthreads();

        uint32_t sbase = sb + st * STAGE_B;
#pragma unroll
        for (int p = 0; p < 3; p++) {
            uint32_t Ab = sbase + (pa[p] ? ST_A_LO : ST_A_HI);
            uint32_t Bb = sbase + (pb[p] ? ST_B_LO : ST_B_HI);
#pragma unroll
            for (int ks = 0; ks < 2; ks++) {
                uint32_t a[2][4];
#pragma unroll
                for (int bm = 0; bm < 2; bm++)
                    ldsm_x4(a[bm], Ab + (uint32_t)((wr * 32 + bm * 16 + a_min) * ROWB
                                                   + ks * 32 + a_koff));
                uint32_t b[8][2];
#pragma unroll
                for (int jp = 0; jp < 4; jp++) {
                    uint32_t t[4];
                    ldsm_x4(t, Bb + (uint32_t)((wc * 64 + jp * 16 + b_nin) * ROWB
                                               + ks * 32 + b_koff));
                    b[jp * 2][0]     = t[0];
                    b[jp * 2][1]     = t[1];
                    b[jp * 2 + 1][0] = t[2];
                    b[jp * 2 + 1][1] = t[3];
                }
#pragma unroll
                for (int bm = 0; bm < 2; bm++)
#pragma unroll
                    for (int j = 0; j < 8; j++)
                        mma_bf16(acc[bm][j], a[bm], b[j]);
            }
        }
        __syncthreads();
    }

    int mrow = wr * 32, ncol = wc * 64;
    float cs[16], cs2[16];
#pragma unroll
    for (int t = 0; t < 16; t++) { cs[t] = 0.f; cs2[t] = 0.f; }

#pragma unroll
    for (int bm = 0; bm < 2; bm++) {
        int r_lo = row0 + mrow + bm * 16 + (lane >> 2);
        int r_hi = r_lo + 8;
#pragma unroll
        for (int j = 0; j < 8; j++) {
            int cb = ncol + j * 8 + (lane & 3) * 2;
            float v0 = acc[bm][j][0], v1 = acc[bm][j][1];
            float v2 = acc[bm][j][2], v3 = acc[bm][j][3];
            cs[j * 2]      += v0 + v2;
            cs2[j * 2]     += v0 * v0 + v2 * v2;
            cs[j * 2 + 1]  += v1 + v3;
            cs2[j * 2 + 1] += v1 * v1 + v3 * v3;
            if (r_lo < NN)
                *(float2*)(g_h + (size_t)r_lo * DD + cb) = make_float2(v0, v1);
            if (r_hi < NN)
                *(float2*)(g_h + (size_t)r_hi * DD + cb) = make_float2(v2, v3);
        }
    }
#pragma unroll
    for (int t = 0; t < 16; t++) {
        cs[t]  += __shfl_xor_sync(0xffffffffu, cs[t], 4);
        cs[t]  += __shfl_xor_sync(0xffffffffu, cs[t], 8);
        cs[t]  += __shfl_xor_sync(0xffffffffu, cs[t], 16);
        cs2[t] += __shfl_xor_sync(0xffffffffu, cs2[t], 4);
        cs2[t] += __shfl_xor_sync(0xffffffffu, cs2[t], 8);
        cs2[t] += __shfl_xor_sync(0xffffffffu, cs2[t], 16);
    }
    if (lane < 4) {
#pragma unroll
        for (int j = 0; j < 8; j++) {
#pragma unroll
            for (int t = 0; t < 2; t++) {
                int col = ncol + j * 8 + lane * 2 + t;
                atomicAdd(&ssum[col],  cs[j * 2 + t]);
                atomicAdd(&ssum2[col], cs2[j * 2 + t]);
            }
        }
    }
    __syncthreads();
    float* sums = (float*)g_zr + SUM_OFF + layer * 256;
    if (tid < DD) {
        atomicAdd(&sums[tid],       ssum[tid]);
        atomicAdd(&sums[tid + DD],  ssum2[tid]);
    }
}

// ---------------- BN (stats from per-layer slots) + ReLU + residual ---------
__global__ void bnfin_kernel(int layer,
                             const float* __restrict__ gamma,
                             const float* __restrict__ beta) {
    __shared__ float s_scale[DD], s_shift[DD];
    int tid = threadIdx.x;
    if (tid < DD) {
        const float* sums = (const float*)g_zr + SUM_OFF + layer * 256;
        float invN = 1.0f / (float)NN;
        float mu  = sums[tid] * invN;
        float var = sums[tid + DD] * invN - mu * mu;
        float a   = __ldg(gamma + tid) * rsqrtf(var + 1e-5f);
        s_scale[tid] = a;
        s_shift[tid] = __ldg(beta + tid) - mu * a;
    }
    __syncthreads();

    int i = blockIdx.x * blockDim.x + tid;
    if (i >= NN * 16) return;
    int seg = i & 15;
    uint4 vh = ((const uint4*)g_xhi)[i];
    uint4 vl = ((const uint4*)g_xlo)[i];
    const __nv_bfloat162* ph = (const __nv_bfloat162*)&vh;
    const __nv_bfloat162* pl = (const __nv_bfloat162*)&vl;
    int row = i >> 4;
    const float4* h4 = (const float4*)(g_h + (size_t)row * DD + seg * 8);
    float4 hv0 = h4[0], hv1 = h4[1];

    float xv[8], hh[8];
#pragma unroll
    for (int q = 0; q < 4; q++) {
        float2 fh = __bfloat1622float2(ph[q]);
        float2 fl = __bfloat1622float2(pl[q]);
        xv[2 * q] = fh.x + fl.x; xv[2 * q + 1] = fh.y + fl.y;
    }
    hh[0]=hv0.x; hh[1]=hv0.y; hh[2]=hv0.z; hh[3]=hv0.w;
    hh[4]=hv1.x; hh[5]=hv1.y; hh[6]=hv1.z; hh[7]=hv1.w;

    uint32_t oh[4], ol[4];
#pragma unroll
    for (int q = 0; q < 4; q++) {
        int c0 = seg * 8 + 2 * q, c1 = c0 + 1;
        float o0 = xv[2 * q]     + fmaxf(0.f, hh[2 * q]     * s_scale[c0] + s_shift[c0]);
        float o1 = xv[2 * q + 1] + fmaxf(0.f, hh[2 * q + 1] * s_scale[c1] + s_shift[c1]);
        __nv_bfloat16 h0, l0, h1, l1;
        split_bf16(o0, h0, l0);
        split_bf16(o1, h1, l1);
        __nv_bfloat162 pkh(h0, h1), pkl(l0, l1);
        oh[q] = *(uint32_t*)&pkh;
        ol[q] = *(uint32_t*)&pkl;
    }
    ((uint4*)g_xhi)[i] = make_uint4(oh[0], oh[1], oh[2], oh[3]);
    ((uint4*)g_xlo)[i] = make_uint4(ol[0], ol[1], ol[2], ol[3]);
}

// ---------------- final linear: row/thread, 47 register accumulators --------
__global__ __launch_bounds__(256) void final_kernel(
    const float* __restrict__ W,
    const float* __restrict__ bias,
    float* __restrict__ out) {
    __shared__ float Ws[CC * DD];
    __shared__ float bs[CC];
    int tid = threadIdx.x;
    int row = blockIdx.x * 256 + tid;

    for (int i = tid; i < CC * DD; i += 256) Ws[i] = __ldg(W + i);
    if (tid < CC) bs[tid] = __ldg(bias + tid);
    __syncthreads();

    if (row >= NN) return;

    float acc[CC];
#pragma unroll
    for (int c = 0; c < CC; c++) acc[c] = 0.f;

    for (int kc = 0; kc < 16; kc++) {
        uint4 vh = ((const uint4*)g_xhi)[(size_t)row * 16 + kc];
        uint4 vl = ((const uint4*)g_xlo)[(size_t)row * 16 + kc];
        const __nv_bfloat162* ph = (const __nv_bfloat162*)&vh;
        const __nv_bfloat162* pl = (const __nv_bfloat162*)&vl;
        float f[8];
#pragma unroll
        for (int q = 0; q < 4; q++) {
            float2 a = __bfloat1622float2(ph[q]);
            float2 b = __bfloat1622float2(pl[q]);
            f[2 * q] = a.x + b.x; f[2 * q + 1] = a.y + b.y;
        }
#pragma unroll
        for (int c = 0; c < CC; c++) {
            const float4* wr = (const float4*)&Ws[c * DD + kc * 8];
            float4 w0 = wr[0], w1 = wr[1];
            acc[c] += f[0] * w0.x + f[1] * w0.y + f[2] * w0.z + f[3] * w0.w
                    + f[4] * w1.x + f[5] * w1.y + f[6] * w1.z + f[7] * w1.w;
        }
    }
#pragma unroll
    for (int c = 0; c < CC; c++)
        out[(size_t)row * CC + c] = acc[c] + bs[c];
}

// ---------------- host orchestration ----------------------------------------
extern "C" void kernel_launch(void* const* d_in, const int* in_sizes, int n_in,
                              void* d_out, int out_size) {
    const float* x  = (const float*)d_in[0];
    const int*   ei = (const int*)d_in[1];
    int E = in_sizes[1] / 2;
    const int* src = ei;
    const int* dst = ei + E;

    const int SMEM_MMA = 2 * STAGE_B;
    cudaFuncSetAttribute(gemm_mma_kernel, cudaFuncAttributeMaxDynamicSharedMemorySize, SMEM_MMA);

    // 1-3: conversions + scratch zero
    xconv_kernel<<<(NN * 32 + 255) / 256, 256>>>((const float4*)x);
    wconv_kernel<<<(3 * 2 * DD * DD + 255) / 256, 256>>>(
        (const float*)d_in[2],  (const float*)d_in[4],
        (const float*)d_in[7],  (const float*)d_in[9],
        (const float*)d_in[12], (const float*)d_in[14]);
    zero_kernel<<<(ZR_INTS + 255) / 256, 256>>>();
    // 4: CSR build ← ncu capture slot
    csr_kernel<<<NBLK, 1024>>>(src, dst, E);
    // 5: layer-1 gather
    gather_f32_kernel<<<(NN * 32 + 255) / 256, 256>>>((const float4*)x);

    for (int L = 0; L < 3; L++) {
        const float* bg = (const float*)d_in[5 + 5 * L];
        const float* bb = (const float*)d_in[6 + 5 * L];
        if (L > 0) gather_bf_kernel<<<(NN * 32 + 255) / 256, 256>>>();
        gemm_mma_kernel<<<(NN + 127) / 128, 256, SMEM_MMA>>>(L);
        bnfin_kernel<<<(NN * 16 + 255) / 256, 256>>>(L, bg, bb);
    }

    final_kernel<<<(NN + 255) / 256, 256>>>(
        (const float*)d_in[17], (const float*)d_in[18], (float*)d_out);
}